// round 3
// baseline (speedup 1.0000x reference)
#include <cuda_runtime.h>
#include <math.h>

#define NN 50000
#define NE 800000
#define HD 256

// ---- device scratch (no allocations allowed in kernel_launch) ----
__device__ __align__(16) float g_agg[(size_t)NN * HD];
__device__ __align__(16) float g_h1[(size_t)NN * HD];
__device__ __align__(16) float g_h2[(size_t)NN * HD];
__device__ int   g_rowptr[NN + 1];
__device__ int   g_col[NE];
__device__ int   g_src[NE];
__device__ int   g_dst[NE];
__device__ int   g_cnt[NN];
__device__ int   g_wpos[NN];
__device__ float g_invdeg[NN];
__device__ int   g_is32;     // 1 if edge buffer is int32, 0 if int64

// ---------------- edge dtype probe + conversion ----------------
__global__ void k_zero() {
    int i = blockIdx.x * blockDim.x + threadIdx.x;
    if (i < NN) { g_cnt[i] = 0; g_wpos[i] = 0; }
    if (i == 0) g_is32 = 0;
}

// If buffer is int64 (LE, values < 2^31) every odd int32 word is 0.
// If buffer is int32, odd words are random node indices; any nonzero -> int32.
__global__ void k_detect(const int* __restrict__ e32) {
    int i = blockIdx.x * blockDim.x + threadIdx.x;   // sample 4096 odd words
    if (i < 4096) {
        if (e32[2 * i + 1] != 0) atomicOr(&g_is32, 1);
    }
}

__global__ void k_convert(const int* __restrict__ e32) {
    int i = blockIdx.x * blockDim.x + threadIdx.x;
    if (i >= NE) return;
    int s, d;
    if (g_is32) {
        s = e32[i];
        d = e32[NE + i];
    } else {
        s = e32[2 * i];                // low word of int64 src[i]
        d = e32[2 * (NE + i)];         // low word of int64 dst[i]
    }
    // defensive clamp (reference guarantees in-range)
    if (s < 0) s = 0; if (s >= NN) s = NN - 1;
    if (d < 0) d = 0; if (d >= NN) d = NN - 1;
    g_src[i] = s;
    g_dst[i] = d;
}

// ---------------- CSR build ----------------
__global__ void k_count() {
    int e = blockIdx.x * blockDim.x + threadIdx.x;
    if (e < NE) atomicAdd(&g_cnt[g_dst[e]], 1);
}

// single-CTA two-pass scan over 50000 counts
__global__ void k_scan() {
    __shared__ int ssum[1024];
    int tid = threadIdx.x;
    const int chunk = (NN + 1023) / 1024;   // 49
    int begin = tid * chunk;
    int end = begin + chunk; if (end > NN) end = NN;
    if (begin > NN) begin = NN;
    int s = 0;
    for (int i = begin; i < end; ++i) s += g_cnt[i];
    ssum[tid] = s;
    __syncthreads();
    for (int off = 1; off < 1024; off <<= 1) {
        int v = ssum[tid];
        int u = (tid >= off) ? ssum[tid - off] : 0;
        __syncthreads();
        ssum[tid] = v + u;
        __syncthreads();
    }
    int run = (tid == 0) ? 0 : ssum[tid - 1];
    for (int i = begin; i < end; ++i) { g_rowptr[i] = run; run += g_cnt[i]; }
    if (tid == 1023) g_rowptr[NN] = ssum[1023];
}

__global__ void k_invdeg() {
    int i = blockIdx.x * blockDim.x + threadIdx.x;
    if (i < NN) {
        int d = g_cnt[i];
        g_invdeg[i] = 1.0f / (float)(d > 1 ? d : 1);
    }
}

__global__ void k_fill() {
    int e = blockIdx.x * blockDim.x + threadIdx.x;
    if (e < NE) {
        int d = g_dst[e];
        int p = atomicAdd(&g_wpos[d], 1);
        g_col[g_rowptr[d] + p] = g_src[e];
    }
}

// ---------------- mean aggregation: one warp per dst node ----------------
__global__ void k_agg(const float* __restrict__ x) {
    int warp = (blockIdx.x * blockDim.x + threadIdx.x) >> 5;
    int lane = threadIdx.x & 31;
    if (warp >= NN) return;
    int s = g_rowptr[warp], e = g_rowptr[warp + 1];
    float4 a0 = make_float4(0.f, 0.f, 0.f, 0.f);
    float4 a1 = make_float4(0.f, 0.f, 0.f, 0.f);
    for (int i = s; i < e; ++i) {
        int c = g_col[i];
        const float4* row = (const float4*)(x + (size_t)c * HD);
        float4 v0 = row[lane];        // cols [lane*4, lane*4+4)
        float4 v1 = row[lane + 32];   // cols [128+lane*4, ...)
        a0.x += v0.x; a0.y += v0.y; a0.z += v0.z; a0.w += v0.w;
        a1.x += v1.x; a1.y += v1.y; a1.z += v1.z; a1.w += v1.w;
    }
    float sc = g_invdeg[warp];
    a0.x *= sc; a0.y *= sc; a0.z *= sc; a0.w *= sc;
    a1.x *= sc; a1.y *= sc; a1.z *= sc; a1.w *= sc;
    float4* dst = (float4*)(g_agg + (size_t)warp * HD);
    dst[lane] = a0;
    dst[lane + 32] = a1;
}

// ---------------- fused GEMM + bias + ELU ----------------
// out[m,n] = ELU( sum_k agg[m,k]*Wl[n,k] + sum_k in[m,k]*Wr[n,k] + bias[n] )
// 128x128 block tile, BK=8, 256 threads, 8x8 microtile per thread.
__global__ __launch_bounds__(256, 2)
void k_gemm(const float* __restrict__ Aagg, const float* __restrict__ Ain,
            const float* __restrict__ Wl,   const float* __restrict__ Wr,
            const float* __restrict__ bias, float* __restrict__ out, int M)
{
    __shared__ float As[8][128];
    __shared__ float Bs[8][128];
    const int bm = blockIdx.x * 128;
    const int bn = blockIdx.y * 128;
    const int tid = threadIdx.x;
    const int lrow = tid >> 1;          // 0..127
    const int lcol = (tid & 1) * 4;     // 0 or 4
    const int tx = tid & 15;            // n-tile coord
    const int ty = tid >> 4;            // m-tile coord

    float acc[8][8];
#pragma unroll
    for (int i = 0; i < 8; ++i)
#pragma unroll
        for (int j = 0; j < 8; ++j) acc[i][j] = 0.f;

    for (int srcsel = 0; srcsel < 2; ++srcsel) {
        const float* A = srcsel ? Ain : Aagg;
        const float* W = srcsel ? Wr : Wl;
        for (int k0 = 0; k0 < HD; k0 += 8) {
            float4 av = make_float4(0.f, 0.f, 0.f, 0.f);
            int gm = bm + lrow;
            if (gm < M) av = *(const float4*)(A + (size_t)gm * HD + k0 + lcol);
            As[lcol + 0][lrow] = av.x;
            As[lcol + 1][lrow] = av.y;
            As[lcol + 2][lrow] = av.z;
            As[lcol + 3][lrow] = av.w;
            float4 bv = *(const float4*)(W + (size_t)(bn + lrow) * HD + k0 + lcol);
            Bs[lcol + 0][lrow] = bv.x;
            Bs[lcol + 1][lrow] = bv.y;
            Bs[lcol + 2][lrow] = bv.z;
            Bs[lcol + 3][lrow] = bv.w;
            __syncthreads();
#pragma unroll
            for (int k = 0; k < 8; ++k) {
                float4 a04 = *(const float4*)&As[k][ty * 8];
                float4 a14 = *(const float4*)&As[k][ty * 8 + 4];
                float4 b04 = *(const float4*)&Bs[k][tx * 8];
                float4 b14 = *(const float4*)&Bs[k][tx * 8 + 4];
                float ar[8] = {a04.x, a04.y, a04.z, a04.w, a14.x, a14.y, a14.z, a14.w};
                float br[8] = {b04.x, b04.y, b04.z, b04.w, b14.x, b14.y, b14.z, b14.w};
#pragma unroll
                for (int i = 0; i < 8; ++i)
#pragma unroll
                    for (int j = 0; j < 8; ++j)
                        acc[i][j] = fmaf(ar[i], br[j], acc[i][j]);
            }
            __syncthreads();
        }
    }

    // epilogue: bias + ELU + store
#pragma unroll
    for (int i = 0; i < 8; ++i) {
        int gm = bm + ty * 8 + i;
        if (gm < M) {
            float vals[8];
#pragma unroll
            for (int j = 0; j < 8; ++j) {
                int gn = bn + tx * 8 + j;
                float v = acc[i][j] + bias[gn];
                vals[j] = (v > 0.f) ? v : expm1f(v);
            }
            float4* po = (float4*)(out + (size_t)gm * HD + bn + tx * 8);
            po[0] = make_float4(vals[0], vals[1], vals[2], vals[3]);
            po[1] = make_float4(vals[4], vals[5], vals[6], vals[7]);
        }
    }
}

// ---------------- launch ----------------
extern "C" void kernel_launch(void* const* d_in, const int* in_sizes, int n_in,
                              void* d_out, int out_size)
{
    const float* x = nullptr;
    const int* edge32 = nullptr;     // raw edge buffer viewed as int32 words
    const float* W[6] = {};
    const float* B[3] = {};
    int wi = 0, bi = 0;
    for (int i = 0; i < n_in; ++i) {
        int s = in_sizes[i];
        if (s == NN * HD)            x = (const float*)d_in[i];
        else if (s == 2 * NE)        edge32 = (const int*)d_in[i];
        else if (s == HD * HD) { if (wi < 6) W[wi++] = (const float*)d_in[i]; }
        else if (s == HD)      { if (bi < 3) B[bi++] = (const float*)d_in[i]; }
    }
    float* out = (float*)d_out;

    float *agg_p, *h1_p, *h2_p;
    cudaGetSymbolAddress((void**)&agg_p, g_agg);
    cudaGetSymbolAddress((void**)&h1_p, g_h1);
    cudaGetSymbolAddress((void**)&h2_p, g_h2);

    // edge dtype probe + normalize to int32 src/dst
    k_zero<<<(NN + 255) / 256, 256>>>();
    k_detect<<<(4096 + 255) / 256, 256>>>(edge32);
    k_convert<<<(NE + 255) / 256, 256>>>(edge32);

    // CSR build (once; graph shared by all 3 layers)
    k_count<<<(NE + 255) / 256, 256>>>();
    k_scan<<<1, 1024>>>();
    k_invdeg<<<(NN + 255) / 256, 256>>>();
    k_fill<<<(NE + 255) / 256, 256>>>();

    const int aggBlocks = (NN + 7) / 8;        // 8 warps/CTA, warp per node
    dim3 ggrid((NN + 127) / 128, HD / 128);    // 391 x 2

    // layer 1: x -> h1
    k_agg<<<aggBlocks, 256>>>(x);
    k_gemm<<<ggrid, 256>>>(agg_p, x, W[0], W[1], B[0], h1_p, NN);
    // layer 2: h1 -> h2
    k_agg<<<aggBlocks, 256>>>(h1_p);
    k_gemm<<<ggrid, 256>>>(agg_p, h1_p, W[2], W[3], B[1], h2_p, NN);
    // layer 3: h2 -> out
    k_agg<<<aggBlocks, 256>>>(h2_p);
    k_gemm<<<ggrid, 256>>>(agg_p, h2_p, W[4], W[5], B[2], out, NN);
}

// round 10
// speedup vs baseline: 1.6725x; 1.6725x over previous
#include <cuda_runtime.h>
#include <math.h>
#include <stdint.h>

#define NN 50000
#define NE 800000
#define HD 256
#define MPAD 50048            // 391 * 128
#define NCH 24                // 3 segments * 8 chunks of 64 bf16 cols (K=512 total)
#define STAGE_BYTES 32768     // A 16KB + B 16KB per stage
#define SMEM_TOTAL (3 * STAGE_BYTES)

// ---- device scratch ----
// agg features (written by k_agg, read by gemm)
__device__ __align__(16) unsigned short g_AGh[(size_t)MPAD * HD];
__device__ __align__(16) unsigned short g_AGl[(size_t)MPAD * HD];
// input features ping/pong (layer L reads one, writes the other -> no race)
__device__ __align__(16) unsigned short g_X0h[(size_t)MPAD * HD];
__device__ __align__(16) unsigned short g_X0l[(size_t)MPAD * HD];
__device__ __align__(16) unsigned short g_X1h[(size_t)MPAD * HD];
__device__ __align__(16) unsigned short g_X1l[(size_t)MPAD * HD];
// weights: [layer][n][k] with k = [Wl 0..255 | Wr 256..511]
__device__ __align__(16) unsigned short g_Bh[3 * 256 * 512];
__device__ __align__(16) unsigned short g_Bl[3 * 256 * 512];
__device__ int   g_rowptr[NN + 1];
__device__ int   g_col[NE];
__device__ int   g_src[NE];
__device__ int   g_dst[NE];
__device__ int   g_cnt[NN];
__device__ int   g_wpos[NN];
__device__ float g_invdeg[NN];
__device__ int   g_is32;

// ---- helpers ----
__device__ __forceinline__ float bf2f(uint32_t bits16) {
    return __uint_as_float(bits16 << 16);
}
__device__ __forceinline__ uint32_t f2bf(float f) {
    uint32_t u = __float_as_uint(f);
    u += 0x7fffu + ((u >> 16) & 1u);
    return u >> 16;
}
__device__ __forceinline__ void split2(float v, uint32_t& h, uint32_t& l) {
    h = f2bf(v);
    l = f2bf(v - bf2f(h));
}
__device__ __forceinline__ uint32_t smem_u32(const void* p) {
    uint32_t a;
    asm("{ .reg .u64 t; cvta.to.shared.u64 t, %1; cvt.u32.u64 %0, t; }" : "=r"(a) : "l"(p));
    return a;
}
#define SW128(o) ((o) ^ (((o) >> 3) & 0x70))

#define CP16(sm, gp) asm volatile("cp.async.cg.shared.global [%0], [%1], 16;" :: "r"(sm), "l"(gp) : "memory")
#define CP_COMMIT()  asm volatile("cp.async.commit_group;" ::: "memory")
#define CP_WAIT(n)   asm volatile("cp.async.wait_group %0;" :: "n"(n) : "memory")

__device__ __forceinline__ void ldsm4(uint32_t* r, uint32_t addr) {
    asm volatile("ldmatrix.sync.aligned.m8n8.x4.shared.b16 {%0,%1,%2,%3}, [%4];"
        : "=r"(r[0]), "=r"(r[1]), "=r"(r[2]), "=r"(r[3]) : "r"(addr));
}
__device__ __forceinline__ void mma16816(float* c, const uint32_t* a, const uint32_t* b) {
    asm volatile("mma.sync.aligned.m16n8k16.row.col.f32.bf16.bf16.f32 "
        "{%0,%1,%2,%3}, {%4,%5,%6,%7}, {%8,%9}, {%0,%1,%2,%3};"
        : "+f"(c[0]), "+f"(c[1]), "+f"(c[2]), "+f"(c[3])
        : "r"(a[0]), "r"(a[1]), "r"(a[2]), "r"(a[3]), "r"(b[0]), "r"(b[1]));
}

// ---------------- edge dtype probe + conversion ----------------
__global__ void k_zero() {
    int i = blockIdx.x * blockDim.x + threadIdx.x;
    if (i < NN) { g_cnt[i] = 0; g_wpos[i] = 0; }
    if (i == 0) g_is32 = 0;
}

__global__ void k_detect(const int* __restrict__ e32) {
    int i = blockIdx.x * blockDim.x + threadIdx.x;
    if (i < 4096) {
        if (e32[2 * i + 1] != 0) atomicOr(&g_is32, 1);
    }
}

__global__ void k_convert(const int* __restrict__ e32) {
    int i = blockIdx.x * blockDim.x + threadIdx.x;
    if (i >= NE) return;
    int s, d;
    if (g_is32) { s = e32[i]; d = e32[NE + i]; }
    else        { s = e32[2 * i]; d = e32[2 * (NE + i)]; }
    if (s < 0) s = 0; if (s >= NN) s = NN - 1;
    if (d < 0) d = 0; if (d >= NN) d = NN - 1;
    g_src[i] = s;
    g_dst[i] = d;
}

// ---------------- CSR build ----------------
__global__ void k_count() {
    int e = blockIdx.x * blockDim.x + threadIdx.x;
    if (e < NE) atomicAdd(&g_cnt[g_dst[e]], 1);
}

__global__ void k_scan() {
    __shared__ int ssum[1024];
    int tid = threadIdx.x;
    const int chunk = (NN + 1023) / 1024;
    int begin = tid * chunk;
    int end = begin + chunk; if (end > NN) end = NN;
    if (begin > NN) begin = NN;
    int s = 0;
    for (int i = begin; i < end; ++i) s += g_cnt[i];
    ssum[tid] = s;
    __syncthreads();
    for (int off = 1; off < 1024; off <<= 1) {
        int v = ssum[tid];
        int u = (tid >= off) ? ssum[tid - off] : 0;
        __syncthreads();
        ssum[tid] = v + u;
        __syncthreads();
    }
    int run = (tid == 0) ? 0 : ssum[tid - 1];
    for (int i = begin; i < end; ++i) { g_rowptr[i] = run; run += g_cnt[i]; }
    if (tid == 1023) g_rowptr[NN] = ssum[1023];
}

__global__ void k_invdeg() {
    int i = blockIdx.x * blockDim.x + threadIdx.x;
    if (i < NN) {
        int d = g_cnt[i];
        g_invdeg[i] = 1.0f / (float)(d > 1 ? d : 1);
    }
}

__global__ void k_fill() {
    int e = blockIdx.x * blockDim.x + threadIdx.x;
    if (e < NE) {
        int d = g_dst[e];
        int p = atomicAdd(&g_wpos[d], 1);
        g_col[g_rowptr[d] + p] = g_src[e];
    }
}

// ---------------- weight / x conversion ----------------
__global__ void k_wconv(const float* __restrict__ W0, const float* __restrict__ W1,
                        const float* __restrict__ W2, const float* __restrict__ W3,
                        const float* __restrict__ W4, const float* __restrict__ W5) {
    int i = blockIdx.x * blockDim.x + threadIdx.x;
    if (i >= 3 * 256 * 512) return;
    int layer = i / (256 * 512);
    int r = i % (256 * 512);
    int n = r / 512, k = r % 512;
    const float* Wl = (layer == 0) ? W0 : ((layer == 1) ? W2 : W4);
    const float* Wr = (layer == 0) ? W1 : ((layer == 1) ? W3 : W5);
    float v = (k < 256) ? Wl[n * 256 + k] : Wr[n * 256 + (k - 256)];
    uint32_t h, l;
    split2(v, h, l);
    g_Bh[i] = (unsigned short)h;
    g_Bl[i] = (unsigned short)l;
}

__global__ void k_xconv(const float* __restrict__ x) {
    int i = blockIdx.x * blockDim.x + threadIdx.x;
    if (i >= NN * HD) return;
    uint32_t h, l;
    split2(x[i], h, l);
    g_X0h[i] = (unsigned short)h;
    g_X0l[i] = (unsigned short)l;
}

// ---------------- mean aggregation: one warp per dst node ----------------
// reads input features (bf16 hi+lo), writes split agg into g_AG*
__global__ void k_agg(const unsigned short* __restrict__ inh,
                      const unsigned short* __restrict__ inl) {
    int warp = (blockIdx.x * blockDim.x + threadIdx.x) >> 5;
    int lane = threadIdx.x & 31;
    if (warp >= NN) return;
    int s = g_rowptr[warp], e = g_rowptr[warp + 1];
    float acc[8];
#pragma unroll
    for (int j = 0; j < 8; ++j) acc[j] = 0.f;
    for (int i = s; i < e; ++i) {
        int c = g_col[i];
        size_t base = (size_t)c * HD + lane * 8;
        uint4 vh = *(const uint4*)(inh + base);
        uint4 vl = *(const uint4*)(inl + base);
        acc[0] += bf2f(vh.x & 0xffff) + bf2f(vl.x & 0xffff);
        acc[1] += bf2f(vh.x >> 16)    + bf2f(vl.x >> 16);
        acc[2] += bf2f(vh.y & 0xffff) + bf2f(vl.y & 0xffff);
        acc[3] += bf2f(vh.y >> 16)    + bf2f(vl.y >> 16);
        acc[4] += bf2f(vh.z & 0xffff) + bf2f(vl.z & 0xffff);
        acc[5] += bf2f(vh.z >> 16)    + bf2f(vl.z >> 16);
        acc[6] += bf2f(vh.w & 0xffff) + bf2f(vl.w & 0xffff);
        acc[7] += bf2f(vh.w >> 16)    + bf2f(vl.w >> 16);
    }
    float sc = g_invdeg[warp];
    uint32_t wh[4], wl[4];
#pragma unroll
    for (int p = 0; p < 4; ++p) {
        float v0 = acc[2 * p] * sc, v1 = acc[2 * p + 1] * sc;
        uint32_t h0, l0, h1, l1;
        split2(v0, h0, l0);
        split2(v1, h1, l1);
        wh[p] = h0 | (h1 << 16);
        wl[p] = l0 | (l1 << 16);
    }
    size_t o = (size_t)warp * HD + lane * 8;
    *(uint4*)(g_AGh + o) = make_uint4(wh[0], wh[1], wh[2], wh[3]);
    *(uint4*)(g_AGl + o) = make_uint4(wl[0], wl[1], wl[2], wl[3]);
}

// ---------------- HMMA GEMM + bias + ELU (+fused next-layer split) ----------------
// K = [agg 0..255 | input 0..255] = 512; bf16 hi/lo, 3 MMA segments:
//   seg0 Ah*Bh, seg1 Al*Bh, seg2 Ah*Bl
// CTA tile 128x128, 8 warps of 64x32, chunks of 64 cols, 3-stage cp.async.
// Reads Xin, writes Xout (ping/pong) -> no RAW race between sibling CTAs.
__global__ __launch_bounds__(256, 2)
void k_gemm_mma(int layer, const float* __restrict__ bias,
                float* __restrict__ outp, int final_layer,
                const unsigned short* __restrict__ Xinh,
                const unsigned short* __restrict__ Xinl,
                unsigned short* __restrict__ Xouth,
                unsigned short* __restrict__ Xoutl) {
    extern __shared__ char smem[];
    const uint32_t sbase = smem_u32(smem);
    const int tid = threadIdx.x;
    const int bm = blockIdx.x * 128;
    const int bn = blockIdx.y * 128;
    const int wid = tid >> 5, lane = tid & 31;
    const int wm = (wid & 1) * 64;
    const int wn = (wid >> 1) * 32;

    const unsigned short* BhL = g_Bh + (size_t)layer * 256 * 512;
    const unsigned short* BlL = g_Bl + (size_t)layer * 256 * 512;

    float acc[4][4][4];
#pragma unroll
    for (int a = 0; a < 4; ++a)
#pragma unroll
        for (int b = 0; b < 4; ++b)
#pragma unroll
            for (int c = 0; c < 4; ++c) acc[a][b][c] = 0.f;

    const int frow = tid >> 1;          // fill row 0..127
    const int fpart = tid & 1;          // which 4 of 8 16B pieces

#define FILL_CHUNK(cc) do {                                                     \
        int _c = (cc);                                                          \
        int _st = _c % 3, _seg = _c >> 3, _kc = _c & 7;                         \
        const unsigned short* _Asrc;                                            \
        if (_kc < 4) {                                                          \
            _Asrc = ((_seg == 1) ? g_AGl : g_AGh)                               \
                    + (size_t)(bm + frow) * HD + _kc * 64;                      \
        } else {                                                                \
            _Asrc = ((_seg == 1) ? Xinl : Xinh)                                 \
                    + (size_t)(bm + frow) * HD + (_kc - 4) * 64;                \
        }                                                                       \
        const unsigned short* _Bsrc = ((_seg == 2) ? BlL : BhL)                 \
                    + (size_t)(bn + frow) * 512 + _kc * 64;                     \
        uint32_t _sA = sbase + _st * STAGE_BYTES;                               \
        uint32_t _sB = _sA + 16384;                                             \
        _Pragma("unroll")                                                       \
        for (int _j = 0; _j < 4; ++_j) {                                        \
            int _c16 = fpart * 4 + _j;                                          \
            CP16(_sA + SW128(frow * 128 + _c16 * 16), (const char*)_Asrc + _c16 * 16); \
            CP16(_sB + SW128(frow * 128 + _c16 * 16), (const char*)_Bsrc + _c16 * 16); \
        }                                                                       \
        CP_COMMIT();                                                            \
    } while (0)

    // ldmatrix address components
    const int arow = wm + (lane & 15);
    const int akoff = (lane >> 4) * 8;                       // halfwords
    const int brow = wn + (lane & 7) + ((lane >> 4) << 3);
    const int bkoff = ((lane >> 3) & 1) * 8;

    FILL_CHUNK(0);
    FILL_CHUNK(1);

    for (int c = 0; c < NCH; ++c) {
        if (c + 2 < NCH) FILL_CHUNK(c + 2);
        else CP_COMMIT();                 // empty group keeps wait arithmetic uniform
        CP_WAIT(2);
        __syncthreads();

        const int st = c % 3;
        const uint32_t sA = sbase + st * STAGE_BYTES;
        const uint32_t sB = sA + 16384;
#pragma unroll
        for (int k16 = 0; k16 < 4; ++k16) {
            uint32_t afr[4][4], bfr[2][4];
#pragma unroll
            for (int mi = 0; mi < 4; ++mi)
                ldsm4(afr[mi], sA + SW128((arow + mi * 16) * 128 + (k16 * 16 + akoff) * 2));
#pragma unroll
            for (int nt = 0; nt < 2; ++nt)
                ldsm4(bfr[nt], sB + SW128((brow + nt * 16) * 128 + (k16 * 16 + bkoff) * 2));
#pragma unroll
            for (int mi = 0; mi < 4; ++mi)
#pragma unroll
                for (int ni = 0; ni < 4; ++ni)
                    mma16816(acc[mi][ni], afr[mi], &bfr[ni >> 1][(ni & 1) * 2]);
        }
        __syncthreads();
    }
#undef FILL_CHUNK

    // ---- epilogue: bias + ELU, direct register stores ----
    const int r0 = lane >> 2;
    const int c01 = (lane & 3) * 2;
#pragma unroll
    for (int mi = 0; mi < 4; ++mi) {
#pragma unroll
        for (int half = 0; half < 2; ++half) {
            int m = bm + wm + mi * 16 + r0 + half * 8;
            if (m >= NN) continue;
#pragma unroll
            for (int ni = 0; ni < 4; ++ni) {
                int gn = bn + wn + ni * 8 + c01;
                float v0 = acc[mi][ni][half * 2 + 0] + bias[gn];
                float v1 = acc[mi][ni][half * 2 + 1] + bias[gn + 1];
                v0 = (v0 > 0.f) ? v0 : expm1f(v0);
                v1 = (v1 > 0.f) ? v1 : expm1f(v1);
                if (final_layer) {
                    *(float2*)(outp + (size_t)m * HD + gn) = make_float2(v0, v1);
                } else {
                    uint32_t h0, l0, h1, l1;
                    split2(v0, h0, l0);
                    split2(v1, h1, l1);
                    size_t o = (size_t)m * HD + gn;
                    *(uint32_t*)(Xouth + o) = h0 | (h1 << 16);
                    *(uint32_t*)(Xoutl + o) = l0 | (l1 << 16);
                }
            }
        }
    }
}

// ---------------- launch ----------------
extern "C" void kernel_launch(void* const* d_in, const int* in_sizes, int n_in,
                              void* d_out, int out_size)
{
    const float* x = nullptr;
    const int* edge32 = nullptr;
    const float* W[6] = {};
    const float* B[3] = {};
    int wi = 0, bi = 0;
    for (int i = 0; i < n_in; ++i) {
        int s = in_sizes[i];
        if (s == NN * HD)            x = (const float*)d_in[i];
        else if (s == 2 * NE)        edge32 = (const int*)d_in[i];
        else if (s == HD * HD) { if (wi < 6) W[wi++] = (const float*)d_in[i]; }
        else if (s == HD)      { if (bi < 3) B[bi++] = (const float*)d_in[i]; }
    }
    float* out = (float*)d_out;

    unsigned short *x0h, *x0l, *x1h, *x1l;
    cudaGetSymbolAddress((void**)&x0h, g_X0h);
    cudaGetSymbolAddress((void**)&x0l, g_X0l);
    cudaGetSymbolAddress((void**)&x1h, g_X1h);
    cudaGetSymbolAddress((void**)&x1l, g_X1l);

    cudaFuncSetAttribute(k_gemm_mma, cudaFuncAttributeMaxDynamicSharedMemorySize, SMEM_TOTAL);

    // edge dtype probe + normalize to int32 src/dst
    k_zero<<<(NN + 255) / 256, 256>>>();
    k_detect<<<(4096 + 255) / 256, 256>>>(edge32);
    k_convert<<<(NE + 255) / 256, 256>>>(edge32);

    // CSR build (once; graph shared by all 3 layers)
    k_count<<<(NE + 255) / 256, 256>>>();
    k_scan<<<1, 1024>>>();
    k_invdeg<<<(NN + 255) / 256, 256>>>();
    k_fill<<<(NE + 255) / 256, 256>>>();

    // weight + input conversion to bf16 hi/lo
    k_wconv<<<(3 * 256 * 512 + 255) / 256, 256>>>(W[0], W[1], W[2], W[3], W[4], W[5]);
    k_xconv<<<(NN * HD + 255) / 256, 256>>>(x);

    const int aggBlocks = (NN + 7) / 8;     // 8 warps/CTA, warp per node
    dim3 ggrid(MPAD / 128, 2);              // 391 x 2

    // layer 1: X0 -> X1
    k_agg<<<aggBlocks, 256>>>(x0h, x0l);
    k_gemm_mma<<<ggrid, 256, SMEM_TOTAL>>>(0, B[0], out, 0, x0h, x0l, x1h, x1l);
    // layer 2: X1 -> X0
    k_agg<<<aggBlocks, 256>>>(x1h, x1l);
    k_gemm_mma<<<ggrid, 256, SMEM_TOTAL>>>(1, B[1], out, 0, x1h, x1l, x0h, x0l);
    // layer 3: X0 -> out
    k_agg<<<aggBlocks, 256>>>(x0h, x0l);
    k_gemm_mma<<<ggrid, 256, SMEM_TOTAL>>>(2, B[2], out, 1, x0h, x0l, x1h, x1l);
}

// round 11
// speedup vs baseline: 2.4441x; 1.4614x over previous
#include <cuda_runtime.h>
#include <cuda_fp16.h>
#include <math.h>
#include <stdint.h>

#define NN 50000
#define NE 800000
#define HD 256
#define MPAD 50048            // 391 * 128
#define NCH 8                 // 8 chunks of 64 fp16 cols (K=512); each does Bh+Bl MMA
#define STAGE_BYTES 49152     // A 16KB + Bh 16KB + Bl 16KB
#define SMEM_TOTAL (2 * STAGE_BYTES)

// ---- device scratch (fp16 features; B split hi/lo fp16) ----
__device__ __align__(16) unsigned short g_AG[(size_t)MPAD * HD];
__device__ __align__(16) unsigned short g_X0[(size_t)MPAD * HD];
__device__ __align__(16) unsigned short g_X1[(size_t)MPAD * HD];
// weights: [layer][n][k] with k = [Wl 0..255 | Wr 256..511]
__device__ __align__(16) unsigned short g_Bh[3 * 256 * 512];
__device__ __align__(16) unsigned short g_Bl[3 * 256 * 512];
__device__ int   g_rowptr[NN + 1];
__device__ int   g_col[NE];
__device__ int   g_src[NE];
__device__ int   g_dst[NE];
__device__ int   g_cnt[NN];
__device__ int   g_wpos[NN];
__device__ float g_invdeg[NN];
__device__ int   g_is32;

// ---- helpers ----
__device__ __forceinline__ unsigned short f2h(float v) {
    return __half_as_ushort(__float2half_rn(v));
}
__device__ __forceinline__ float h2f(unsigned short u) {
    return __half2float(__ushort_as_half(u));
}
__device__ __forceinline__ uint32_t smem_u32(const void* p) {
    uint32_t a;
    asm("{ .reg .u64 t; cvta.to.shared.u64 t, %1; cvt.u32.u64 %0, t; }" : "=r"(a) : "l"(p));
    return a;
}
#define SW128(o) ((o) ^ (((o) >> 3) & 0x70))

#define CP16(sm, gp) asm volatile("cp.async.cg.shared.global [%0], [%1], 16;" :: "r"(sm), "l"(gp) : "memory")
#define CP_COMMIT()  asm volatile("cp.async.commit_group;" ::: "memory")
#define CP_WAIT(n)   asm volatile("cp.async.wait_group %0;" :: "n"(n) : "memory")

__device__ __forceinline__ void ldsm4(uint32_t* r, uint32_t addr) {
    asm volatile("ldmatrix.sync.aligned.m8n8.x4.shared.b16 {%0,%1,%2,%3}, [%4];"
        : "=r"(r[0]), "=r"(r[1]), "=r"(r[2]), "=r"(r[3]) : "r"(addr));
}
__device__ __forceinline__ void mma16816(float* c, const uint32_t* a, const uint32_t* b) {
    asm volatile("mma.sync.aligned.m16n8k16.row.col.f32.f16.f16.f32 "
        "{%0,%1,%2,%3}, {%4,%5,%6,%7}, {%8,%9}, {%0,%1,%2,%3};"
        : "+f"(c[0]), "+f"(c[1]), "+f"(c[2]), "+f"(c[3])
        : "r"(a[0]), "r"(a[1]), "r"(a[2]), "r"(a[3]), "r"(b[0]), "r"(b[1]));
}

// ---------------- edge dtype probe + conversion ----------------
__global__ void k_zero() {
    int i = blockIdx.x * blockDim.x + threadIdx.x;
    if (i < NN) { g_cnt[i] = 0; g_wpos[i] = 0; }
    if (i == 0) g_is32 = 0;
}

__global__ void k_detect(const int* __restrict__ e32) {
    int i = blockIdx.x * blockDim.x + threadIdx.x;
    if (i < 4096) {
        if (e32[2 * i + 1] != 0) atomicOr(&g_is32, 1);
    }
}

// convert + degree count fused
__global__ void k_convert_count(const int* __restrict__ e32) {
    int i = blockIdx.x * blockDim.x + threadIdx.x;
    if (i >= NE) return;
    int s, d;
    if (g_is32) { s = e32[i]; d = e32[NE + i]; }
    else        { s = e32[2 * i]; d = e32[2 * (NE + i)]; }
    if (s < 0) s = 0; if (s >= NN) s = NN - 1;
    if (d < 0) d = 0; if (d >= NN) d = NN - 1;
    g_src[i] = s;
    g_dst[i] = d;
    atomicAdd(&g_cnt[d], 1);
}

// single-CTA scan over 50000 counts (+ invdeg fused)
__global__ void k_scan() {
    __shared__ int ssum[1024];
    int tid = threadIdx.x;
    const int chunk = (NN + 1023) / 1024;
    int begin = tid * chunk;
    int end = begin + chunk; if (end > NN) end = NN;
    if (begin > NN) begin = NN;
    int s = 0;
    for (int i = begin; i < end; ++i) s += g_cnt[i];
    ssum[tid] = s;
    __syncthreads();
    for (int off = 1; off < 1024; off <<= 1) {
        int v = ssum[tid];
        int u = (tid >= off) ? ssum[tid - off] : 0;
        __syncthreads();
        ssum[tid] = v + u;
        __syncthreads();
    }
    int run = (tid == 0) ? 0 : ssum[tid - 1];
    for (int i = begin; i < end; ++i) {
        g_rowptr[i] = run;
        int d = g_cnt[i];
        run += d;
        g_invdeg[i] = 1.0f / (float)(d > 1 ? d : 1);
    }
    if (tid == 1023) g_rowptr[NN] = ssum[1023];
}

__global__ void k_fill() {
    int e = blockIdx.x * blockDim.x + threadIdx.x;
    if (e < NE) {
        int d = g_dst[e];
        int p = atomicAdd(&g_wpos[d], 1);
        g_col[g_rowptr[d] + p] = g_src[e];
    }
}

// ---------------- weight / x conversion ----------------
__global__ void k_wconv(const float* __restrict__ W0, const float* __restrict__ W1,
                        const float* __restrict__ W2, const float* __restrict__ W3,
                        const float* __restrict__ W4, const float* __restrict__ W5) {
    int i = blockIdx.x * blockDim.x + threadIdx.x;
    if (i >= 3 * 256 * 512) return;
    int layer = i / (256 * 512);
    int r = i % (256 * 512);
    int n = r / 512, k = r % 512;
    const float* Wl = (layer == 0) ? W0 : ((layer == 1) ? W2 : W4);
    const float* Wr = (layer == 0) ? W1 : ((layer == 1) ? W3 : W5);
    float v = (k < 256) ? Wl[n * 256 + k] : Wr[n * 256 + (k - 256)];
    unsigned short h = f2h(v);
    unsigned short l = f2h(v - h2f(h));
    g_Bh[i] = h;
    g_Bl[i] = l;
}

__global__ void k_xconv(const float* __restrict__ x) {
    int i = blockIdx.x * blockDim.x + threadIdx.x;
    if (i >= NN * HD) return;
    g_X0[i] = f2h(x[i]);
}

// ---------------- mean aggregation: one warp per dst node ----------------
// reads fp16 features (512B/row), fp32 accumulate, writes fp16 agg
__global__ void k_agg(const unsigned short* __restrict__ in) {
    int warp = (blockIdx.x * blockDim.x + threadIdx.x) >> 5;
    int lane = threadIdx.x & 31;
    if (warp >= NN) return;
    int s = g_rowptr[warp], e = g_rowptr[warp + 1];
    float acc[8];
#pragma unroll
    for (int j = 0; j < 8; ++j) acc[j] = 0.f;
    for (int i = s; i < e; ++i) {
        int c = g_col[i];
        const uint4 v = *(const uint4*)(in + (size_t)c * HD + lane * 8);
        float2 p;
        p = __half22float2(*(const __half2*)&v.x); acc[0] += p.x; acc[1] += p.y;
        p = __half22float2(*(const __half2*)((const char*)&v.x + 4)); acc[2] += p.x; acc[3] += p.y;
        p = __half22float2(*(const __half2*)&v.z); acc[4] += p.x; acc[5] += p.y;
        p = __half22float2(*(const __half2*)((const char*)&v.z + 4)); acc[6] += p.x; acc[7] += p.y;
    }
    float sc = g_invdeg[warp];
    uint32_t w[4];
#pragma unroll
    for (int p2 = 0; p2 < 4; ++p2) {
        __half2 h = __floats2half2_rn(acc[2 * p2] * sc, acc[2 * p2 + 1] * sc);
        w[p2] = *(uint32_t*)&h;
    }
    *(uint4*)(g_AG + (size_t)warp * HD + lane * 8) = make_uint4(w[0], w[1], w[2], w[3]);
}

// ---------------- HMMA GEMM + bias + ELU (fp16 A, split-fp16 B) ----------------
// out[m,n] = ELU( A[m,:]·(Bh[n,:]+Bl[n,:]) + bias[n] ),  A=[agg|x] K=512 fp16.
// CTA tile 128x128, 8 warps of 64x32, 8 chunks of 64 cols; per chunk the A tile
// in SMEM is used twice (x Bh, x Bl). 2-stage cp.async pipeline, 2 CTAs/SM.
__global__ __launch_bounds__(256, 2)
void k_gemm_mma(int layer, const float* __restrict__ bias,
                float* __restrict__ outp, int final_layer,
                const unsigned short* __restrict__ Xin,
                unsigned short* __restrict__ Xout) {
    extern __shared__ char smem[];
    const uint32_t sbase = smem_u32(smem);
    const int tid = threadIdx.x;
    const int bm = blockIdx.x * 128;
    const int bn = blockIdx.y * 128;
    const int wid = tid >> 5, lane = tid & 31;
    const int wm = (wid & 1) * 64;
    const int wn = (wid >> 1) * 32;

    const unsigned short* BhL = g_Bh + (size_t)layer * 256 * 512;
    const unsigned short* BlL = g_Bl + (size_t)layer * 256 * 512;

    float acc[4][4][4];
#pragma unroll
    for (int a = 0; a < 4; ++a)
#pragma unroll
        for (int b = 0; b < 4; ++b)
#pragma unroll
            for (int c = 0; c < 4; ++c) acc[a][b][c] = 0.f;

    const int frow = tid >> 1;          // fill row 0..127
    const int fpart = tid & 1;          // which 4 of 8 16B pieces

#define FILL_CHUNK(cc) do {                                                     \
        int _c = (cc);                                                          \
        int _st = _c & 1;                                                       \
        const unsigned short* _Asrc = (_c < 4)                                  \
            ? (g_AG + (size_t)(bm + frow) * HD + _c * 64)                       \
            : (Xin + (size_t)(bm + frow) * HD + (_c - 4) * 64);                 \
        const unsigned short* _Bhs = BhL + (size_t)(bn + frow) * 512 + _c * 64; \
        const unsigned short* _Bls = BlL + (size_t)(bn + frow) * 512 + _c * 64; \
        uint32_t _sA = sbase + _st * STAGE_BYTES;                               \
        _Pragma("unroll")                                                       \
        for (int _j = 0; _j < 4; ++_j) {                                        \
            int _c16 = fpart * 4 + _j;                                          \
            uint32_t _so = SW128(frow * 128 + _c16 * 16);                       \
            CP16(_sA + _so,         (const char*)_Asrc + _c16 * 16);            \
            CP16(_sA + 16384 + _so, (const char*)_Bhs + _c16 * 16);             \
            CP16(_sA + 32768 + _so, (const char*)_Bls + _c16 * 16);             \
        }                                                                       \
        CP_COMMIT();                                                            \
    } while (0)

    // ldmatrix address components
    const int arow = wm + (lane & 15);
    const int akoff = (lane >> 4) * 8;                       // halfwords
    const int brow = wn + (lane & 7) + ((lane >> 4) << 3);
    const int bkoff = ((lane >> 3) & 1) * 8;

    FILL_CHUNK(0);

    for (int c = 0; c < NCH; ++c) {
        if (c + 1 < NCH) FILL_CHUNK(c + 1);
        else CP_COMMIT();                 // empty group keeps wait arithmetic uniform
        CP_WAIT(1);
        __syncthreads();

        const uint32_t sA = sbase + (c & 1) * STAGE_BYTES;
        const uint32_t sBh = sA + 16384;
        const uint32_t sBl = sA + 32768;
#pragma unroll
        for (int k16 = 0; k16 < 4; ++k16) {
            uint32_t afr[4][4], bh[2][4], bl[2][4];
#pragma unroll
            for (int mi = 0; mi < 4; ++mi)
                ldsm4(afr[mi], sA + SW128((arow + mi * 16) * 128 + (k16 * 16 + akoff) * 2));
#pragma unroll
            for (int nt = 0; nt < 2; ++nt) {
                uint32_t off = SW128((brow + nt * 16) * 128 + (k16 * 16 + bkoff) * 2);
                ldsm4(bh[nt], sBh + off);
                ldsm4(bl[nt], sBl + off);
            }
#pragma unroll
            for (int mi = 0; mi < 4; ++mi)
#pragma unroll
                for (int ni = 0; ni < 4; ++ni) {
                    mma16816(acc[mi][ni], afr[mi], &bh[ni >> 1][(ni & 1) * 2]);
                    mma16816(acc[mi][ni], afr[mi], &bl[ni >> 1][(ni & 1) * 2]);
                }
        }
        __syncthreads();
    }
#undef FILL_CHUNK

    // ---- epilogue: bias + ELU, direct register stores ----
    const int r0 = lane >> 2;
    const int c01 = (lane & 3) * 2;
#pragma unroll
    for (int mi = 0; mi < 4; ++mi) {
#pragma unroll
        for (int half = 0; half < 2; ++half) {
            int m = bm + wm + mi * 16 + r0 + half * 8;
            if (m >= NN) continue;
#pragma unroll
            for (int ni = 0; ni < 4; ++ni) {
                int gn = bn + wn + ni * 8 + c01;
                float v0 = acc[mi][ni][half * 2 + 0] + bias[gn];
                float v1 = acc[mi][ni][half * 2 + 1] + bias[gn + 1];
                v0 = (v0 > 0.f) ? v0 : expm1f(v0);
                v1 = (v1 > 0.f) ? v1 : expm1f(v1);
                if (final_layer) {
                    *(float2*)(outp + (size_t)m * HD + gn) = make_float2(v0, v1);
                } else {
                    __half2 hv = __floats2half2_rn(v0, v1);
                    *(uint32_t*)(Xout + (size_t)m * HD + gn) = *(uint32_t*)&hv;
                }
            }
        }
    }
}

// ---------------- launch ----------------
extern "C" void kernel_launch(void* const* d_in, const int* in_sizes, int n_in,
                              void* d_out, int out_size)
{
    const float* x = nullptr;
    const int* edge32 = nullptr;
    const float* W[6] = {};
    const float* B[3] = {};
    int wi = 0, bi = 0;
    for (int i = 0; i < n_in; ++i) {
        int s = in_sizes[i];
        if (s == NN * HD)            x = (const float*)d_in[i];
        else if (s == 2 * NE)        edge32 = (const int*)d_in[i];
        else if (s == HD * HD) { if (wi < 6) W[wi++] = (const float*)d_in[i]; }
        else if (s == HD)      { if (bi < 3) B[bi++] = (const float*)d_in[i]; }
    }
    float* out = (float*)d_out;

    unsigned short *x0, *x1;
    cudaGetSymbolAddress((void**)&x0, g_X0);
    cudaGetSymbolAddress((void**)&x1, g_X1);

    cudaFuncSetAttribute(k_gemm_mma, cudaFuncAttributeMaxDynamicSharedMemorySize, SMEM_TOTAL);

    // edge dtype probe + normalize to int32 src/dst (+ degree count fused)
    k_zero<<<(NN + 255) / 256, 256>>>();
    k_detect<<<(4096 + 255) / 256, 256>>>(edge32);
    k_convert_count<<<(NE + 255) / 256, 256>>>(edge32);

    // CSR build (once; graph shared by all 3 layers)
    k_scan<<<1, 1024>>>();
    k_fill<<<(NE + 255) / 256, 256>>>();

    // weight + input conversion to fp16
    k_wconv<<<(3 * 256 * 512 + 255) / 256, 256>>>(W[0], W[1], W[2], W[3], W[4], W[5]);
    k_xconv<<<(NN * HD + 255) / 256, 256>>>(x);

    const int aggBlocks = (NN + 7) / 8;     // 8 warps/CTA, warp per node
    dim3 ggrid(MPAD / 128, 2);              // 391 x 2

    // layer 1: X0 -> X1
    k_agg<<<aggBlocks, 256>>>(x0);
    k_gemm_mma<<<ggrid, 256, SMEM_TOTAL>>>(0, B[0], out, 0, x0, x1);
    // layer 2: X1 -> X0
    k_agg<<<aggBlocks, 256>>>(x1);
    k_gemm_mma<<<ggrid, 256, SMEM_TOTAL>>>(1, B[1], out, 0, x1, x0);
    // layer 3: X0 -> out
    k_agg<<<aggBlocks, 256>>>(x0);
    k_gemm_mma<<<ggrid, 256, SMEM_TOTAL>>>(2, B[2], out, 1, x0, x1);
}

// round 14
// speedup vs baseline: 2.7797x; 1.1373x over previous
#include <cuda_runtime.h>
#include <cuda_fp16.h>
#include <math.h>
#include <stdint.h>

#define NN 50000
#define NE 800000
#define HD 256
#define MPAD 50048            // 391 * 128
#define NCH 8                 // 8 chunks of 64 fp16 cols (K=512); each does Bh+Bl MMA
#define STAGE_BYTES 49152     // A 16KB + Bh 16KB + Bl 16KB
#define SMEM_TOTAL (2 * STAGE_BYTES)
#define NBLK 196              // scan blocks (196*256 = 50176 >= NN)

// ---- device scratch (fp16 features; B split hi/lo fp16) ----
__device__ __align__(16) unsigned short g_AG[(size_t)MPAD * HD];
__device__ __align__(16) unsigned short g_X0[(size_t)MPAD * HD];
__device__ __align__(16) unsigned short g_X1[(size_t)MPAD * HD];
// weights: [layer][n][k] with k = [Wl 0..255 | Wr 256..511]
__device__ __align__(16) unsigned short g_Bh[3 * 256 * 512];
__device__ __align__(16) unsigned short g_Bl[3 * 256 * 512];
__device__ int   g_rowptr[NN + 1];
__device__ int   g_col[NE];
__device__ int   g_src[NE];
__device__ int   g_dst[NE];
__device__ int   g_cnt[NN];
__device__ int   g_wpos[NN];
__device__ int   g_part[NBLK];
__device__ float g_invdeg[NN];
__device__ int   g_is32;

// ---- helpers ----
__device__ __forceinline__ unsigned short f2h(float v) {
    return __half_as_ushort(__float2half_rn(v));
}
__device__ __forceinline__ float h2f(unsigned short u) {
    return __half2float(__ushort_as_half(u));
}
__device__ __forceinline__ uint32_t smem_u32(const void* p) {
    uint32_t a;
    asm("{ .reg .u64 t; cvta.to.shared.u64 t, %1; cvt.u32.u64 %0, t; }" : "=r"(a) : "l"(p));
    return a;
}
#define SW128(o) ((o) ^ (((o) >> 3) & 0x70))

#define CP16(sm, gp) asm volatile("cp.async.cg.shared.global [%0], [%1], 16;" :: "r"(sm), "l"(gp) : "memory")
#define CP_COMMIT()  asm volatile("cp.async.commit_group;" ::: "memory")
#define CP_WAIT(n)   asm volatile("cp.async.wait_group %0;" :: "n"(n) : "memory")

__device__ __forceinline__ void ldsm4(uint32_t* r, uint32_t addr) {
    asm volatile("ldmatrix.sync.aligned.m8n8.x4.shared.b16 {%0,%1,%2,%3}, [%4];"
        : "=r"(r[0]), "=r"(r[1]), "=r"(r[2]), "=r"(r[3]) : "r"(addr));
}
__device__ __forceinline__ void mma16816(float* c, const uint32_t* a, const uint32_t* b) {
    asm volatile("mma.sync.aligned.m16n8k16.row.col.f32.f16.f16.f32 "
        "{%0,%1,%2,%3}, {%4,%5,%6,%7}, {%8,%9}, {%0,%1,%2,%3};"
        : "+f"(c[0]), "+f"(c[1]), "+f"(c[2]), "+f"(c[3])
        : "r"(a[0]), "r"(a[1]), "r"(a[2]), "r"(a[3]), "r"(b[0]), "r"(b[1]));
}

// ---------------- edge dtype probe + conversion ----------------
__global__ void k_zero() {
    int i = blockIdx.x * blockDim.x + threadIdx.x;
    if (i < NN) { g_cnt[i] = 0; g_wpos[i] = 0; }
    if (i == 0) g_is32 = 0;
}

__global__ void k_detect(const int* __restrict__ e32) {
    int i = blockIdx.x * blockDim.x + threadIdx.x;
    if (i < 4096) {
        if (e32[2 * i + 1] != 0) atomicOr(&g_is32, 1);
    }
}

// convert + degree count fused
__global__ void k_convert_count(const int* __restrict__ e32) {
    int i = blockIdx.x * blockDim.x + threadIdx.x;
    if (i >= NE) return;
    int s, d;
    if (g_is32) { s = e32[i]; d = e32[NE + i]; }
    else        { s = e32[2 * i]; d = e32[2 * (NE + i)]; }
    if (s < 0) s = 0; if (s >= NN) s = NN - 1;
    if (d < 0) d = 0; if (d >= NN) d = NN - 1;
    g_src[i] = s;
    g_dst[i] = d;
    atomicAdd(&g_cnt[d], 1);
}

// ---------------- parallel 3-phase scan ----------------
// phase 1: per-block sums of 256 counts
__global__ void k_blocksum() {
    __shared__ int sh[256];
    int i = blockIdx.x * 256 + threadIdx.x;
    int v = (i < NN) ? g_cnt[i] : 0;
    sh[threadIdx.x] = v;
    __syncthreads();
#pragma unroll
    for (int off = 128; off > 0; off >>= 1) {
        if (threadIdx.x < off) sh[threadIdx.x] += sh[threadIdx.x + off];
        __syncthreads();
    }
    if (threadIdx.x == 0) g_part[blockIdx.x] = sh[0];
}

// phase 2: exclusive scan of NBLK partials (one CTA, 256 threads)
__global__ void k_scanpart() {
    __shared__ int sh[256];
    int tid = threadIdx.x;
    int v = (tid < NBLK) ? g_part[tid] : 0;
    sh[tid] = v;
    __syncthreads();
#pragma unroll
    for (int off = 1; off < 256; off <<= 1) {
        int u = (tid >= off) ? sh[tid - off] : 0;
        __syncthreads();
        sh[tid] += u;
        __syncthreads();
    }
    if (tid < NBLK) g_part[tid] = sh[tid] - v;   // exclusive
    if (tid == 255) g_rowptr[NN] = sh[255];
}

// phase 3: local exclusive scan + block offset -> rowptr (+ invdeg fused)
__global__ void k_rowptr() {
    __shared__ int sh[256];
    int tid = threadIdx.x;
    int i = blockIdx.x * 256 + tid;
    int v = (i < NN) ? g_cnt[i] : 0;
    sh[tid] = v;
    __syncthreads();
#pragma unroll
    for (int off = 1; off < 256; off <<= 1) {
        int u = (tid >= off) ? sh[tid - off] : 0;
        __syncthreads();
        sh[tid] += u;
        __syncthreads();
    }
    if (i < NN) {
        g_rowptr[i] = g_part[blockIdx.x] + sh[tid] - v;   // exclusive
        g_invdeg[i] = 1.0f / (float)(v > 1 ? v : 1);
    }
}

__global__ void k_fill() {
    int e = blockIdx.x * blockDim.x + threadIdx.x;
    if (e < NE) {
        int d = g_dst[e];
        int p = atomicAdd(&g_wpos[d], 1);
        g_col[g_rowptr[d] + p] = g_src[e];
    }
}

// ---------------- weight / x conversion ----------------
__global__ void k_wconv(const float* __restrict__ W0, const float* __restrict__ W1,
                        const float* __restrict__ W2, const float* __restrict__ W3,
                        const float* __restrict__ W4, const float* __restrict__ W5) {
    int i = blockIdx.x * blockDim.x + threadIdx.x;
    if (i >= 3 * 256 * 512) return;
    int layer = i / (256 * 512);
    int r = i % (256 * 512);
    int n = r / 512, k = r % 512;
    const float* Wl = (layer == 0) ? W0 : ((layer == 1) ? W2 : W4);
    const float* Wr = (layer == 0) ? W1 : ((layer == 1) ? W3 : W5);
    float v = (k < 256) ? Wl[n * 256 + k] : Wr[n * 256 + (k - 256)];
    unsigned short h = f2h(v);
    unsigned short l = f2h(v - h2f(h));
    g_Bh[i] = h;
    g_Bl[i] = l;
}

__global__ void k_xconv(const float* __restrict__ x) {
    int i = blockIdx.x * blockDim.x + threadIdx.x;
    if (i >= NN * HD) return;
    g_X0[i] = f2h(x[i]);
}

// ---------------- mean aggregation: one warp per dst node ----------------
// reads fp16 features (512B/row), fp32 accumulate, writes fp16 agg
__global__ void k_agg(const unsigned short* __restrict__ in) {
    int warp = (blockIdx.x * blockDim.x + threadIdx.x) >> 5;
    int lane = threadIdx.x & 31;
    if (warp >= NN) return;
    int s = g_rowptr[warp], e = g_rowptr[warp + 1];
    float acc[8];
#pragma unroll
    for (int j = 0; j < 8; ++j) acc[j] = 0.f;
    for (int i = s; i < e; ++i) {
        int c = g_col[i];
        const uint4 v = *(const uint4*)(in + (size_t)c * HD + lane * 8);
        float2 p;
        p = __half22float2(*(const __half2*)&v.x); acc[0] += p.x; acc[1] += p.y;
        p = __half22float2(*(const __half2*)((const char*)&v.x + 4)); acc[2] += p.x; acc[3] += p.y;
        p = __half22float2(*(const __half2*)&v.z); acc[4] += p.x; acc[5] += p.y;
        p = __half22float2(*(const __half2*)((const char*)&v.z + 4)); acc[6] += p.x; acc[7] += p.y;
    }
    float sc = g_invdeg[warp];
    uint32_t w[4];
#pragma unroll
    for (int p2 = 0; p2 < 4; ++p2) {
        __half2 h = __floats2half2_rn(acc[2 * p2] * sc, acc[2 * p2 + 1] * sc);
        w[p2] = *(uint32_t*)&h;
    }
    *(uint4*)(g_AG + (size_t)warp * HD + lane * 8) = make_uint4(w[0], w[1], w[2], w[3]);
}

// ---------------- HMMA GEMM + bias + ELU (fp16 A, split-fp16 B) ----------------
// out[m,n] = ELU( A[m,:]·(Bh[n,:]+Bl[n,:]) + bias[n] ),  A=[agg|x] K=512 fp16.
// CTA tile 128x128, 8 warps of 64x32, 8 chunks of 64 cols; per chunk the A tile
// in SMEM is used twice (x Bh, x Bl). 2-stage cp.async pipeline, 2 CTAs/SM.
__global__ __launch_bounds__(256, 2)
void k_gemm_mma(int layer, const float* __restrict__ bias,
                float* __restrict__ outp, int final_layer,
                const unsigned short* __restrict__ Xin,
                unsigned short* __restrict__ Xout) {
    extern __shared__ char smem[];
    const uint32_t sbase = smem_u32(smem);
    const int tid = threadIdx.x;
    const int bm = blockIdx.x * 128;
    const int bn = blockIdx.y * 128;
    const int wid = tid >> 5, lane = tid & 31;
    const int wm = (wid & 1) * 64;
    const int wn = (wid >> 1) * 32;

    const unsigned short* BhL = g_Bh + (size_t)layer * 256 * 512;
    const unsigned short* BlL = g_Bl + (size_t)layer * 256 * 512;

    float acc[4][4][4];
#pragma unroll
    for (int a = 0; a < 4; ++a)
#pragma unroll
        for (int b = 0; b < 4; ++b)
#pragma unroll
            for (int c = 0; c < 4; ++c) acc[a][b][c] = 0.f;

    const int frow = tid >> 1;          // fill row 0..127
    const int fpart = tid & 1;          // which 4 of 8 16B pieces

#define FILL_CHUNK(cc) do {                                                     \
        int _c = (cc);                                                          \
        int _st = _c & 1;                                                       \
        const unsigned short* _Asrc = (_c < 4)                                  \
            ? (g_AG + (size_t)(bm + frow) * HD + _c * 64)                       \
            : (Xin + (size_t)(bm + frow) * HD + (_c - 4) * 64);                 \
        const unsigned short* _Bhs = BhL + (size_t)(bn + frow) * 512 + _c * 64; \
        const unsigned short* _Bls = BlL + (size_t)(bn + frow) * 512 + _c * 64; \
        uint32_t _sA = sbase + _st * STAGE_BYTES;                               \
        _Pragma("unroll")                                                       \
        for (int _j = 0; _j < 4; ++_j) {                                        \
            int _c16 = fpart * 4 + _j;                                          \
            uint32_t _so = SW128(frow * 128 + _c16 * 16);                       \
            CP16(_sA + _so,         (const char*)_Asrc + _c16 * 16);            \
            CP16(_sA + 16384 + _so, (const char*)_Bhs + _c16 * 16);             \
            CP16(_sA + 32768 + _so, (const char*)_Bls + _c16 * 16);             \
        }                                                                       \
        CP_COMMIT();                                                            \
    } while (0)

    // ldmatrix address components
    const int arow = wm + (lane & 15);
    const int akoff = (lane >> 4) * 8;                       // halfwords
    const int brow = wn + (lane & 7) + ((lane >> 4) << 3);
    const int bkoff = ((lane >> 3) & 1) * 8;

    FILL_CHUNK(0);

    for (int c = 0; c < NCH; ++c) {
        if (c + 1 < NCH) FILL_CHUNK(c + 1);
        else CP_COMMIT();                 // empty group keeps wait arithmetic uniform
        CP_WAIT(1);
        __syncthreads();

        const uint32_t sA = sbase + (c & 1) * STAGE_BYTES;
        const uint32_t sBh = sA + 16384;
        const uint32_t sBl = sA + 32768;
#pragma unroll
        for (int k16 = 0; k16 < 4; ++k16) {
            uint32_t afr[4][4], bh[2][4], bl[2][4];
#pragma unroll
            for (int mi = 0; mi < 4; ++mi)
                ldsm4(afr[mi], sA + SW128((arow + mi * 16) * 128 + (k16 * 16 + akoff) * 2));
#pragma unroll
            for (int nt = 0; nt < 2; ++nt) {
                uint32_t off = SW128((brow + nt * 16) * 128 + (k16 * 16 + bkoff) * 2);
                ldsm4(bh[nt], sBh + off);
                ldsm4(bl[nt], sBl + off);
            }
#pragma unroll
            for (int mi = 0; mi < 4; ++mi)
#pragma unroll
                for (int ni = 0; ni < 4; ++ni) {
                    mma16816(acc[mi][ni], afr[mi], &bh[ni >> 1][(ni & 1) * 2]);
                    mma16816(acc[mi][ni], afr[mi], &bl[ni >> 1][(ni & 1) * 2]);
                }
        }
        __syncthreads();
    }
#undef FILL_CHUNK

    // ---- epilogue: bias + ELU, direct register stores ----
    const int r0 = lane >> 2;
    const int c01 = (lane & 3) * 2;
#pragma unroll
    for (int mi = 0; mi < 4; ++mi) {
#pragma unroll
        for (int half = 0; half < 2; ++half) {
            int m = bm + wm + mi * 16 + r0 + half * 8;
            if (m >= NN) continue;
#pragma unroll
            for (int ni = 0; ni < 4; ++ni) {
                int gn = bn + wn + ni * 8 + c01;
                float v0 = acc[mi][ni][half * 2 + 0] + bias[gn];
                float v1 = acc[mi][ni][half * 2 + 1] + bias[gn + 1];
                v0 = (v0 > 0.f) ? v0 : expm1f(v0);
                v1 = (v1 > 0.f) ? v1 : expm1f(v1);
                if (final_layer) {
                    *(float2*)(outp + (size_t)m * HD + gn) = make_float2(v0, v1);
                } else {
                    __half2 hv = __floats2half2_rn(v0, v1);
                    *(uint32_t*)(Xout + (size_t)m * HD + gn) = *(uint32_t*)&hv;
                }
            }
        }
    }
}

// ---------------- launch ----------------
extern "C" void kernel_launch(void* const* d_in, const int* in_sizes, int n_in,
                              void* d_out, int out_size)
{
    const float* x = nullptr;
    const int* edge32 = nullptr;
    const float* W[6] = {};
    const float* B[3] = {};
    int wi = 0, bi = 0;
    for (int i = 0; i < n_in; ++i) {
        int s = in_sizes[i];
        if (s == NN * HD)            x = (const float*)d_in[i];
        else if (s == 2 * NE)        edge32 = (const int*)d_in[i];
        else if (s == HD * HD) { if (wi < 6) W[wi++] = (const float*)d_in[i]; }
        else if (s == HD)      { if (bi < 3) B[bi++] = (const float*)d_in[i]; }
    }
    float* out = (float*)d_out;

    unsigned short *x0, *x1;
    cudaGetSymbolAddress((void**)&x0, g_X0);
    cudaGetSymbolAddress((void**)&x1, g_X1);

    cudaFuncSetAttribute(k_gemm_mma, cudaFuncAttributeMaxDynamicSharedMemorySize, SMEM_TOTAL);

    // edge dtype probe + normalize to int32 src/dst (+ degree count fused)
    k_zero<<<(NN + 255) / 256, 256>>>();
    k_detect<<<(4096 + 255) / 256, 256>>>(edge32);
    k_convert_count<<<(NE + 255) / 256, 256>>>(edge32);

    // CSR build: parallel 3-phase scan + fill
    k_blocksum<<<NBLK, 256>>>();
    k_scanpart<<<1, 256>>>();
    k_rowptr<<<NBLK, 256>>>();
    k_fill<<<(NE + 255) / 256, 256>>>();

    // weight + input conversion to fp16
    k_wconv<<<(3 * 256 * 512 + 255) / 256, 256>>>(W[0], W[1], W[2], W[3], W[4], W[5]);
    k_xconv<<<(NN * HD + 255) / 256, 256>>>(x);

    const int aggBlocks = (NN + 7) / 8;     // 8 warps/CTA, warp per node
    dim3 ggrid(MPAD / 128, 2);              // 391 x 2

    // layer 1: X0 -> X1
    k_agg<<<aggBlocks, 256>>>(x0);
    k_gemm_mma<<<ggrid, 256, SMEM_TOTAL>>>(0, B[0], out, 0, x0, x1);
    // layer 2: X1 -> X0
    k_agg<<<aggBlocks, 256>>>(x1);
    k_gemm_mma<<<ggrid, 256, SMEM_TOTAL>>>(1, B[1], out, 0, x1, x0);
    // layer 3: X0 -> out
    k_agg<<<aggBlocks, 256>>>(x0);
    k_gemm_mma<<<ggrid, 256, SMEM_TOTAL>>>(2, B[2], out, 1, x0, x1);
}

// round 15
// speedup vs baseline: 3.5126x; 1.2637x over previous
#include <cuda_runtime.h>
#include <cuda_fp16.h>
#include <math.h>
#include <stdint.h>

#define NN 50000
#define NE 800000
#define HD 256
#define MPAD 50048            // 391 * 128
#define NCH 8                 // 8 chunks of 64 fp16 cols (K=512)
#define STAGE_BYTES 32768     // A 16KB + B 16KB per stage
#define SMEM_TOTAL (2 * STAGE_BYTES)
#define NBLK 196              // scan blocks (196*256 = 50176 >= NN)

// ---- device scratch (fp16 features + fp16 weights) ----
__device__ __align__(16) unsigned short g_AG[(size_t)MPAD * HD];
__device__ __align__(16) unsigned short g_X0[(size_t)MPAD * HD];
__device__ __align__(16) unsigned short g_X1[(size_t)MPAD * HD];
// weights: [layer][n][k] with k = [Wl 0..255 | Wr 256..511]
__device__ __align__(16) unsigned short g_B[3 * 256 * 512];
__device__ int   g_rowptr[NN + 1];
__device__ int   g_col[NE];
__device__ int   g_src[NE];
__device__ int   g_dst[NE];
__device__ int   g_cnt[NN];
__device__ int   g_wpos[NN];
__device__ int   g_part[NBLK];
__device__ float g_invdeg[NN];
__device__ int   g_is32;

// ---- helpers ----
__device__ __forceinline__ unsigned short f2h(float v) {
    return __half_as_ushort(__float2half_rn(v));
}
__device__ __forceinline__ uint32_t smem_u32(const void* p) {
    uint32_t a;
    asm("{ .reg .u64 t; cvta.to.shared.u64 t, %1; cvt.u32.u64 %0, t; }" : "=r"(a) : "l"(p));
    return a;
}
#define SW128(o) ((o) ^ (((o) >> 3) & 0x70))

#define CP16(sm, gp) asm volatile("cp.async.cg.shared.global [%0], [%1], 16;" :: "r"(sm), "l"(gp) : "memory")
#define CP_COMMIT()  asm volatile("cp.async.commit_group;" ::: "memory")
#define CP_WAIT(n)   asm volatile("cp.async.wait_group %0;" :: "n"(n) : "memory")

__device__ __forceinline__ void ldsm4(uint32_t* r, uint32_t addr) {
    asm volatile("ldmatrix.sync.aligned.m8n8.x4.shared.b16 {%0,%1,%2,%3}, [%4];"
        : "=r"(r[0]), "=r"(r[1]), "=r"(r[2]), "=r"(r[3]) : "r"(addr));
}
__device__ __forceinline__ void mma16816(float* c, const uint32_t* a, const uint32_t* b) {
    asm volatile("mma.sync.aligned.m16n8k16.row.col.f32.f16.f16.f32 "
        "{%0,%1,%2,%3}, {%4,%5,%6,%7}, {%8,%9}, {%0,%1,%2,%3};"
        : "+f"(c[0]), "+f"(c[1]), "+f"(c[2]), "+f"(c[3])
        : "r"(a[0]), "r"(a[1]), "r"(a[2]), "r"(a[3]), "r"(b[0]), "r"(b[1]));
}

// ---------------- edge dtype probe + conversion ----------------
__global__ void k_zero() {
    int i = blockIdx.x * blockDim.x + threadIdx.x;
    if (i < NN) { g_cnt[i] = 0; g_wpos[i] = 0; }
    if (i == 0) g_is32 = 0;
}

__global__ void k_detect(const int* __restrict__ e32) {
    int i = blockIdx.x * blockDim.x + threadIdx.x;
    if (i < 4096) {
        if (e32[2 * i + 1] != 0) atomicOr(&g_is32, 1);
    }
}

// convert + degree count fused
__global__ void k_convert_count(const int* __restrict__ e32) {
    int i = blockIdx.x * blockDim.x + threadIdx.x;
    if (i >= NE) return;
    int s, d;
    if (g_is32) { s = e32[i]; d = e32[NE + i]; }
    else        { s = e32[2 * i]; d = e32[2 * (NE + i)]; }
    if (s < 0) s = 0; if (s >= NN) s = NN - 1;
    if (d < 0) d = 0; if (d >= NN) d = NN - 1;
    g_src[i] = s;
    g_dst[i] = d;
    atomicAdd(&g_cnt[d], 1);
}

// ---------------- parallel 3-phase scan ----------------
__global__ void k_blocksum() {
    __shared__ int sh[256];
    int i = blockIdx.x * 256 + threadIdx.x;
    int v = (i < NN) ? g_cnt[i] : 0;
    sh[threadIdx.x] = v;
    __syncthreads();
#pragma unroll
    for (int off = 128; off > 0; off >>= 1) {
        if (threadIdx.x < off) sh[threadIdx.x] += sh[threadIdx.x + off];
        __syncthreads();
    }
    if (threadIdx.x == 0) g_part[blockIdx.x] = sh[0];
}

__global__ void k_scanpart() {
    __shared__ int sh[256];
    int tid = threadIdx.x;
    int v = (tid < NBLK) ? g_part[tid] : 0;
    sh[tid] = v;
    __syncthreads();
#pragma unroll
    for (int off = 1; off < 256; off <<= 1) {
        int u = (tid >= off) ? sh[tid - off] : 0;
        __syncthreads();
        sh[tid] += u;
        __syncthreads();
    }
    if (tid < NBLK) g_part[tid] = sh[tid] - v;   // exclusive
    if (tid == 255) g_rowptr[NN] = sh[255];
}

__global__ void k_rowptr() {
    __shared__ int sh[256];
    int tid = threadIdx.x;
    int i = blockIdx.x * 256 + tid;
    int v = (i < NN) ? g_cnt[i] : 0;
    sh[tid] = v;
    __syncthreads();
#pragma unroll
    for (int off = 1; off < 256; off <<= 1) {
        int u = (tid >= off) ? sh[tid - off] : 0;
        __syncthreads();
        sh[tid] += u;
        __syncthreads();
    }
    if (i < NN) {
        g_rowptr[i] = g_part[blockIdx.x] + sh[tid] - v;   // exclusive
        g_invdeg[i] = 1.0f / (float)(v > 1 ? v : 1);
    }
}

__global__ void k_fill() {
    int e = blockIdx.x * blockDim.x + threadIdx.x;
    if (e < NE) {
        int d = g_dst[e];
        int p = atomicAdd(&g_wpos[d], 1);
        g_col[g_rowptr[d] + p] = g_src[e];
    }
}

// ---------------- weight / x conversion ----------------
__global__ void k_wconv(const float* __restrict__ W0, const float* __restrict__ W1,
                        const float* __restrict__ W2, const float* __restrict__ W3,
                        const float* __restrict__ W4, const float* __restrict__ W5) {
    int i = blockIdx.x * blockDim.x + threadIdx.x;
    if (i >= 3 * 256 * 512) return;
    int layer = i / (256 * 512);
    int r = i % (256 * 512);
    int n = r / 512, k = r % 512;
    const float* Wl = (layer == 0) ? W0 : ((layer == 1) ? W2 : W4);
    const float* Wr = (layer == 0) ? W1 : ((layer == 1) ? W3 : W5);
    float v = (k < 256) ? Wl[n * 256 + k] : Wr[n * 256 + (k - 256)];
    g_B[i] = f2h(v);
}

__global__ void k_xconv(const float* __restrict__ x) {
    int i = blockIdx.x * blockDim.x + threadIdx.x;
    if (i >= NN * HD) return;
    g_X0[i] = f2h(x[i]);
}

// ---------------- mean aggregation: one warp per dst node ----------------
__global__ void k_agg(const unsigned short* __restrict__ in) {
    int warp = (blockIdx.x * blockDim.x + threadIdx.x) >> 5;
    int lane = threadIdx.x & 31;
    if (warp >= NN) return;
    int s = g_rowptr[warp], e = g_rowptr[warp + 1];
    float acc[8];
#pragma unroll
    for (int j = 0; j < 8; ++j) acc[j] = 0.f;
    for (int i = s; i < e; ++i) {
        int c = g_col[i];
        const uint4 v = *(const uint4*)(in + (size_t)c * HD + lane * 8);
        float2 p;
        p = __half22float2(*(const __half2*)&v.x); acc[0] += p.x; acc[1] += p.y;
        p = __half22float2(*(const __half2*)((const char*)&v.x + 4)); acc[2] += p.x; acc[3] += p.y;
        p = __half22float2(*(const __half2*)&v.z); acc[4] += p.x; acc[5] += p.y;
        p = __half22float2(*(const __half2*)((const char*)&v.z + 4)); acc[6] += p.x; acc[7] += p.y;
    }
    float sc = g_invdeg[warp];
    uint32_t w[4];
#pragma unroll
    for (int p2 = 0; p2 < 4; ++p2) {
        __half2 h = __floats2half2_rn(acc[2 * p2] * sc, acc[2 * p2 + 1] * sc);
        w[p2] = *(uint32_t*)&h;
    }
    *(uint4*)(g_AG + (size_t)warp * HD + lane * 8) = make_uint4(w[0], w[1], w[2], w[3]);
}

// ---------------- HMMA GEMM + bias + ELU (fp16 A, fp16 B) ----------------
// out[m,n] = ELU( A[m,:]·B[n,:] + bias[n] ),  A=[agg|x] K=512 fp16.
// CTA tile 128x128, 8 warps of 64x32, 8 chunks of 64 cols, 2-stage cp.async.
__global__ __launch_bounds__(256, 2)
void k_gemm_mma(int layer, const float* __restrict__ bias,
                float* __restrict__ outp, int final_layer,
                const unsigned short* __restrict__ Xin,
                unsigned short* __restrict__ Xout) {
    extern __shared__ char smem[];
    const uint32_t sbase = smem_u32(smem);
    const int tid = threadIdx.x;
    const int bm = blockIdx.x * 128;
    const int bn = blockIdx.y * 128;
    const int wid = tid >> 5, lane = tid & 31;
    const int wm = (wid & 1) * 64;
    const int wn = (wid >> 1) * 32;

    const unsigned short* BL = g_B + (size_t)layer * 256 * 512;

    float acc[4][4][4];
#pragma unroll
    for (int a = 0; a < 4; ++a)
#pragma unroll
        for (int b = 0; b < 4; ++b)
#pragma unroll
            for (int c = 0; c < 4; ++c) acc[a][b][c] = 0.f;

    const int frow = tid >> 1;          // fill row 0..127
    const int fpart = tid & 1;          // which 4 of 8 16B pieces

#define FILL_CHUNK(cc) do {                                                     \
        int _c = (cc);                                                          \
        int _st = _c & 1;                                                       \
        const unsigned short* _Asrc = (_c < 4)                                  \
            ? (g_AG + (size_t)(bm + frow) * HD + _c * 64)                       \
            : (Xin + (size_t)(bm + frow) * HD + (_c - 4) * 64);                 \
        const unsigned short* _Bs = BL + (size_t)(bn + frow) * 512 + _c * 64;   \
        uint32_t _sA = sbase + _st * STAGE_BYTES;                               \
        _Pragma("unroll")                                                       \
        for (int _j = 0; _j < 4; ++_j) {                                        \
            int _c16 = fpart * 4 + _j;                                          \
            uint32_t _so = SW128(frow * 128 + _c16 * 16);                       \
            CP16(_sA + _so,         (const char*)_Asrc + _c16 * 16);            \
            CP16(_sA + 16384 + _so, (const char*)_Bs + _c16 * 16);              \
        }                                                                       \
        CP_COMMIT();                                                            \
    } while (0)

    // ldmatrix address components
    const int arow = wm + (lane & 15);
    const int akoff = (lane >> 4) * 8;                       // halfwords
    const int brow = wn + (lane & 7) + ((lane >> 4) << 3);
    const int bkoff = ((lane >> 3) & 1) * 8;

    FILL_CHUNK(0);

    for (int c = 0; c < NCH; ++c) {
        if (c + 1 < NCH) FILL_CHUNK(c + 1);
        else CP_COMMIT();                 // empty group keeps wait arithmetic uniform
        CP_WAIT(1);
        __syncthreads();

        const uint32_t sA = sbase + (c & 1) * STAGE_BYTES;
        const uint32_t sB = sA + 16384;
#pragma unroll
        for (int k16 = 0; k16 < 4; ++k16) {
            uint32_t afr[4][4], bfr[2][4];
#pragma unroll
            for (int mi = 0; mi < 4; ++mi)
                ldsm4(afr[mi], sA + SW128((arow + mi * 16) * 128 + (k16 * 16 + akoff) * 2));
#pragma unroll
            for (int nt = 0; nt < 2; ++nt)
                ldsm4(bfr[nt], sB + SW128((brow + nt * 16) * 128 + (k16 * 16 + bkoff) * 2));
#pragma unroll
            for (int mi = 0; mi < 4; ++mi)
#pragma unroll
                for (int ni = 0; ni < 4; ++ni)
                    mma16816(acc[mi][ni], afr[mi], &bfr[ni >> 1][(ni & 1) * 2]);
        }
        __syncthreads();
    }
#undef FILL_CHUNK

    // ---- epilogue: bias + ELU, direct register stores ----
    const int r0 = lane >> 2;
    const int c01 = (lane & 3) * 2;
#pragma unroll
    for (int mi = 0; mi < 4; ++mi) {
#pragma unroll
        for (int half = 0; half < 2; ++half) {
            int m = bm + wm + mi * 16 + r0 + half * 8;
            if (m >= NN) continue;
#pragma unroll
            for (int ni = 0; ni < 4; ++ni) {
                int gn = bn + wn + ni * 8 + c01;
                float v0 = acc[mi][ni][half * 2 + 0] + bias[gn];
                float v1 = acc[mi][ni][half * 2 + 1] + bias[gn + 1];
                v0 = (v0 > 0.f) ? v0 : expm1f(v0);
                v1 = (v1 > 0.f) ? v1 : expm1f(v1);
                if (final_layer) {
                    *(float2*)(outp + (size_t)m * HD + gn) = make_float2(v0, v1);
                } else {
                    __half2 hv = __floats2half2_rn(v0, v1);
                    *(uint32_t*)(Xout + (size_t)m * HD + gn) = *(uint32_t*)&hv;
                }
            }
        }
    }
}

// ---------------- launch ----------------
extern "C" void kernel_launch(void* const* d_in, const int* in_sizes, int n_in,
                              void* d_out, int out_size)
{
    const float* x = nullptr;
    const int* edge32 = nullptr;
    const float* W[6] = {};
    const float* B[3] = {};
    int wi = 0, bi = 0;
    for (int i = 0; i < n_in; ++i) {
        int s = in_sizes[i];
        if (s == NN * HD)            x = (const float*)d_in[i];
        else if (s == 2 * NE)        edge32 = (const int*)d_in[i];
        else if (s == HD * HD) { if (wi < 6) W[wi++] = (const float*)d_in[i]; }
        else if (s == HD)      { if (bi < 3) B[bi++] = (const float*)d_in[i]; }
    }
    float* out = (float*)d_out;

    unsigned short *x0, *x1;
    cudaGetSymbolAddress((void**)&x0, g_X0);
    cudaGetSymbolAddress((void**)&x1, g_X1);

    cudaFuncSetAttribute(k_gemm_mma, cudaFuncAttributeMaxDynamicSharedMemorySize, SMEM_TOTAL);

    // edge dtype probe + normalize to int32 src/dst (+ degree count fused)
    k_zero<<<(NN + 255) / 256, 256>>>();
    k_detect<<<(4096 + 255) / 256, 256>>>(edge32);
    k_convert_count<<<(NE + 255) / 256, 256>>>(edge32);

    // CSR build: parallel 3-phase scan + fill
    k_blocksum<<<NBLK, 256>>>();
    k_scanpart<<<1, 256>>>();
    k_rowptr<<<NBLK, 256>>>();
    k_fill<<<(NE + 255) / 256, 256>>>();

    // weight + input conversion to fp16
    k_wconv<<<(3 * 256 * 512 + 255) / 256, 256>>>(W[0], W[1], W[2], W[3], W[4], W[5]);
    k_xconv<<<(NN * HD + 255) / 256, 256>>>(x);

    const int aggBlocks = (NN + 7) / 8;     // 8 warps/CTA, warp per node
    dim3 ggrid(MPAD / 128, 2);              // 391 x 2

    // layer 1: X0 -> X1
    k_agg<<<aggBlocks, 256>>>(x0);
    k_gemm_mma<<<ggrid, 256, SMEM_TOTAL>>>(0, B[0], out, 0, x0, x1);
    // layer 2: X1 -> X0
    k_agg<<<aggBlocks, 256>>>(x1);
    k_gemm_mma<<<ggrid, 256, SMEM_TOTAL>>>(1, B[1], out, 0, x1, x0);
    // layer 3: X0 -> out
    k_agg<<<aggBlocks, 256>>>(x0);
    k_gemm_mma<<<ggrid, 256, SMEM_TOTAL>>>(2, B[2], out, 1, x0, x1);
}